// round 1
// baseline (speedup 1.0000x reference)
#include <cuda_runtime.h>

#define BB 32
#define TT 256
#define DD 512
#define PP 20
#define EPSV 1e-12f

// Scratch (no cudaMalloc allowed)
__device__ float g_nan[BB * TT * DD];      // l2-normalized inp_a
__device__ float g_nbn[BB * TT * DD];      // l2-normalized inp_b
__device__ float g_alpha[(size_t)BB * DD * DD];
__device__ float g_colpart[BB * 8 * DD];   // partial column sums of squares
__device__ float g_invcol[BB * DD];        // 1/sqrt(max(colsumsq,eps))
__device__ float g_hmean[BB * TT * DD];

// ---------------------------------------------------------------------------
// Kernel 1: row-wise l2 normalize both inputs. One warp per row (D=512).
// ---------------------------------------------------------------------------
__global__ void k_norm(const float* __restrict__ a, const float* __restrict__ b) {
    int gw = (blockIdx.x * blockDim.x + threadIdx.x) >> 5;
    int lane = threadIdx.x & 31;
    if (gw >= 2 * BB * TT) return;
    const float* src;
    float* dst;
    int row;
    if (gw < BB * TT) { src = a; dst = g_nan; row = gw; }
    else              { src = b; dst = g_nbn; row = gw - BB * TT; }

    const float4* s4 = (const float4*)(src + (size_t)row * DD);
    float4 v[4];
    float ss = 0.f;
#pragma unroll
    for (int i = 0; i < 4; i++) {
        v[i] = s4[lane + 32 * i];
        ss += v[i].x * v[i].x + v[i].y * v[i].y + v[i].z * v[i].z + v[i].w * v[i].w;
    }
#pragma unroll
    for (int o = 16; o > 0; o >>= 1) ss += __shfl_xor_sync(0xffffffffu, ss, o);
    float inv = rsqrtf(fmaxf(ss, EPSV));
    float4* d4 = (float4*)(dst + (size_t)row * DD);
#pragma unroll
    for (int i = 0; i < 4; i++) {
        float4 w = v[i];
        w.x *= inv; w.y *= inv; w.z *= inv; w.w *= inv;
        d4[lane + 32 * i] = w;
    }
}

// ---------------------------------------------------------------------------
// Kernel 2: alpha[b,i,j] = sum_t nbn[b,t,i] * nan[b,t,j]
// 64x64 block tile, K-tile 16 over t, 256 threads, 4x4 microtile.
// ---------------------------------------------------------------------------
__global__ void k_gemm1() {
    int b = blockIdx.z;
    const float* __restrict__ A = g_nbn + (size_t)b * TT * DD;   // [T][D]
    const float* __restrict__ Bm = g_nan + (size_t)b * TT * DD;  // [T][D]
    float* __restrict__ C = g_alpha + (size_t)b * DD * DD;
    int i0 = blockIdx.y * 64, j0 = blockIdx.x * 64;

    __shared__ float As[16][64];
    __shared__ float Bs[16][64];

    int tid = threadIdx.x;
    int tx = tid & 15, ty = tid >> 4;
    int lk = tid >> 4;            // k row for loads
    int lc = (tid & 15) << 2;     // col offset (float4)

    float acc[4][4] = {};

    for (int t0 = 0; t0 < TT; t0 += 16) {
        float4 av = *(const float4*)(A + (size_t)(t0 + lk) * DD + i0 + lc);
        float4 bv = *(const float4*)(Bm + (size_t)(t0 + lk) * DD + j0 + lc);
        *(float4*)&As[lk][lc] = av;
        *(float4*)&Bs[lk][lc] = bv;
        __syncthreads();
#pragma unroll
        for (int k = 0; k < 16; k++) {
            float4 a4 = *(const float4*)&As[k][ty << 2];
            float4 b4 = *(const float4*)&Bs[k][tx << 2];
            float ar[4] = {a4.x, a4.y, a4.z, a4.w};
            float br[4] = {b4.x, b4.y, b4.z, b4.w};
#pragma unroll
            for (int r = 0; r < 4; r++)
#pragma unroll
                for (int c = 0; c < 4; c++) acc[r][c] += ar[r] * br[c];
        }
        __syncthreads();
    }
#pragma unroll
    for (int r = 0; r < 4; r++) {
        float4 o = make_float4(acc[r][0], acc[r][1], acc[r][2], acc[r][3]);
        *(float4*)(C + (size_t)(i0 + (ty << 2) + r) * DD + j0 + (tx << 2)) = o;
    }
}

// ---------------------------------------------------------------------------
// Kernel 3a: partial column sums of squares of alpha over d (axis 1).
// grid (B, 8): each block sums 64 d-rows for all 512 e.
// ---------------------------------------------------------------------------
__global__ void k_colpart() {
    int b = blockIdx.x, c = blockIdx.y;
    int e = threadIdx.x; // 512 threads
    const float* __restrict__ Al = g_alpha + (size_t)b * DD * DD;
    float s = 0.f;
    int dbase = c * 64;
#pragma unroll 8
    for (int d = 0; d < 64; d++) {
        float v = Al[(size_t)(dbase + d) * DD + e];
        s += v * v;
    }
    g_colpart[(size_t)((b << 3) + c) * DD + e] = s;
}

// Kernel 3b: reduce the 8 partials -> invcol
__global__ void k_invcol() {
    int i = blockIdx.x * blockDim.x + threadIdx.x; // B*D
    if (i >= BB * DD) return;
    int b = i / DD, e = i - b * DD;
    float s = 0.f;
#pragma unroll
    for (int c = 0; c < 8; c++) s += g_colpart[(size_t)((b << 3) + c) * DD + e];
    g_invcol[i] = rsqrtf(fmaxf(s, EPSV));
}

// ---------------------------------------------------------------------------
// Kernel 4: hmean[b,t,e] = (sum_d nbn[b,t,d] * alpha[b,d,e]) * invcol[b,e]
// 64x64 tile, K-tile 16 over d. A is transposed into shared (contraction is
// A's contiguous dim), padded row stride 68 floats (16B-aligned, conflict-free).
// ---------------------------------------------------------------------------
__global__ void k_gemm2() {
    int b = blockIdx.z;
    const float* __restrict__ A = g_nbn + (size_t)b * TT * DD;    // [T][D]
    const float* __restrict__ Bm = g_alpha + (size_t)b * DD * DD; // [D][E]
    const float* __restrict__ ic = g_invcol + (size_t)b * DD;
    float* __restrict__ C = g_hmean + (size_t)b * TT * DD;
    int t0 = blockIdx.y * 64, e0 = blockIdx.x * 64;

    __shared__ float As[16][68]; // transposed: As[k][m]
    __shared__ float Bs[16][64];

    int tid = threadIdx.x;
    int tx = tid & 15, ty = tid >> 4;
    int am = tid >> 2, ak = (tid & 3) << 2;   // A loader: row m, k offset
    int bk = tid >> 4, bn = (tid & 15) << 2;  // B loader

    float acc[4][4] = {};

    for (int d0 = 0; d0 < DD; d0 += 16) {
        float4 av = *(const float4*)(A + (size_t)(t0 + am) * DD + d0 + ak);
        As[ak + 0][am] = av.x;
        As[ak + 1][am] = av.y;
        As[ak + 2][am] = av.z;
        As[ak + 3][am] = av.w;
        float4 bv = *(const float4*)(Bm + (size_t)(d0 + bk) * DD + e0 + bn);
        *(float4*)&Bs[bk][bn] = bv;
        __syncthreads();
#pragma unroll
        for (int k = 0; k < 16; k++) {
            float4 a4 = *(const float4*)&As[k][ty << 2];
            float4 b4 = *(const float4*)&Bs[k][tx << 2];
            float ar[4] = {a4.x, a4.y, a4.z, a4.w};
            float br[4] = {b4.x, b4.y, b4.z, b4.w};
#pragma unroll
            for (int r = 0; r < 4; r++)
#pragma unroll
                for (int c = 0; c < 4; c++) acc[r][c] += ar[r] * br[c];
        }
        __syncthreads();
    }

    float4 s = *(const float4*)(ic + e0 + (tx << 2));
#pragma unroll
    for (int r = 0; r < 4; r++) {
        float4 o = make_float4(acc[r][0] * s.x, acc[r][1] * s.y,
                               acc[r][2] * s.z, acc[r][3] * s.w);
        *(float4*)(C + (size_t)(t0 + (ty << 2) + r) * DD + e0 + (tx << 2)) = o;
    }
}

// ---------------------------------------------------------------------------
// Kernel 5: perspective scores.
// persp[b,t,p] = S3 / (sqrt(max(S1,eps)) * sqrt(max(S2,eps)))
//   S1 = sum_d a^2 W^2, S2 = sum_d h^2 W^2, S3 = sum_d a h W^2   (a raw, h = hmean)
// One block per (b,t) row; 4 warps, each warp handles 5 perspectives.
// Row (a,h) resident in registers; W cached in L2 (40 KB total).
// ---------------------------------------------------------------------------
__global__ void k_persp(const float* __restrict__ inp_a,
                        const float* __restrict__ W,
                        float* __restrict__ out, int dup) {
    int row = blockIdx.x;                       // b*T + t
    int lane = threadIdx.x & 31;
    int w = threadIdx.x >> 5;                   // warp 0..3

    const float4* a4p = (const float4*)(inp_a + (size_t)row * DD);
    const float4* h4p = (const float4*)(g_hmean + (size_t)row * DD);
    float4 a[4], h[4];
#pragma unroll
    for (int i = 0; i < 4; i++) { a[i] = a4p[lane + 32 * i]; h[i] = h4p[lane + 32 * i]; }

#pragma unroll
    for (int pp = 0; pp < 5; pp++) {
        int p = w * 5 + pp;
        const float4* w4p = (const float4*)(W + (size_t)p * DD);
        float s1 = 0.f, s2 = 0.f, s3 = 0.f;
#pragma unroll
        for (int i = 0; i < 4; i++) {
            float4 wv = w4p[lane + 32 * i];
            float w2;
            w2 = wv.x * wv.x; s1 += a[i].x * a[i].x * w2; s2 += h[i].x * h[i].x * w2; s3 += a[i].x * h[i].x * w2;
            w2 = wv.y * wv.y; s1 += a[i].y * a[i].y * w2; s2 += h[i].y * h[i].y * w2; s3 += a[i].y * h[i].y * w2;
            w2 = wv.z * wv.z; s1 += a[i].z * a[i].z * w2; s2 += h[i].z * h[i].z * w2; s3 += a[i].z * h[i].z * w2;
            w2 = wv.w * wv.w; s1 += a[i].w * a[i].w * w2; s2 += h[i].w * h[i].w * w2; s3 += a[i].w * h[i].w * w2;
        }
#pragma unroll
        for (int o = 16; o > 0; o >>= 1) {
            s1 += __shfl_xor_sync(0xffffffffu, s1, o);
            s2 += __shfl_xor_sync(0xffffffffu, s2, o);
            s3 += __shfl_xor_sync(0xffffffffu, s3, o);
        }
        if (lane == 0) {
            float v = s3 * rsqrtf(fmaxf(s1, EPSV)) * rsqrtf(fmaxf(s2, EPSV));
            out[(size_t)row * PP + p] = v;
            if (dup) out[(size_t)BB * TT * PP + (size_t)row * PP + p] = v;
        }
    }
}

// ---------------------------------------------------------------------------
extern "C" void kernel_launch(void* const* d_in, const int* in_sizes, int n_in,
                              void* d_out, int out_size) {
    const float* inp_a = (const float*)d_in[0];
    const float* inp_b = (const float*)d_in[1];
    const float* W     = (const float*)d_in[2];
    float* out = (float*)d_out;

    int dup = (out_size >= 2 * BB * TT * PP) ? 1 : 0;

    // 1) row l2-normalize (16384 warps)
    k_norm<<<2 * BB * TT / 8, 256>>>(inp_a, inp_b);

    // 2) alpha = nbn^T @ nan per batch
    k_gemm1<<<dim3(DD / 64, DD / 64, BB), 256>>>();

    // 3) column inverse norms of alpha
    k_colpart<<<dim3(BB, 8), DD>>>();
    k_invcol<<<(BB * DD + 255) / 256, 256>>>();

    // 4) hmean = nbn @ (alpha * invcol) per batch
    k_gemm2<<<dim3(DD / 64, TT / 64, BB), 256>>>();

    // 5) perspective scores (duplicated output if needed)
    k_persp<<<BB * TT, 128>>>(inp_a, W, out, dup);
}

// round 3
// speedup vs baseline: 2.0119x; 2.0119x over previous
#include <cuda_runtime.h>
#include <cstdint>

#define BB 32
#define TT 256
#define DD 512
#define PP 20
#define EPSV 1e-12f

// ---------------- scratch (__device__ globals; no cudaMalloc allowed) ------
__device__ float g_nbn [BB * TT * DD];            // normalized b, [b][t][d]
__device__ float g_nbnT[BB * DD * TT];            // normalized b, [b][d][t]
__device__ float g_nanT[BB * DD * TT];            // normalized a, [b][d][t]
__device__ float g_alphaT[(size_t)BB * DD * DD];  // [b][e][d]
__device__ float g_invcol[BB * DD];               // per (b,e)
__device__ float g_hmean[BB * TT * DD];           // [b][t][e]

__device__ __forceinline__ uint32_t f2tf32(float f) {
    uint32_t r;
    asm("cvt.rna.tf32.f32 %0, %1;" : "=r"(r) : "f"(f));
    return r;
}

// ---------------------------------------------------------------------------
// Kernel 1: row l2-normalize + transpose.  Block = 256 thr, tile = 16 t-rows.
// which=0: a -> g_nanT only.  which=1: b -> g_nbn + g_nbnT.
// ---------------------------------------------------------------------------
__global__ void __launch_bounds__(256) k_normT(const float* __restrict__ a,
                                               const float* __restrict__ b) {
    __shared__ float s[16 * 513];
    __shared__ float sinv[16];
    int which = blockIdx.z;
    int bb = blockIdx.y;
    int t0 = blockIdx.x * 16;
    const float* src = (which ? b : a) + ((size_t)bb * TT + t0) * DD;
    int tid = threadIdx.x;

#pragma unroll
    for (int i = 0; i < 8; i++) {
        int idx = tid + i * 256;
        int r = idx >> 7, c4 = idx & 127;
        float4 v = *(const float4*)(src + (size_t)r * DD + c4 * 4);
        float* sr = s + r * 513 + c4 * 4;
        sr[0] = v.x; sr[1] = v.y; sr[2] = v.z; sr[3] = v.w;
    }
    __syncthreads();

    int wid = tid >> 5, lid = tid & 31;
#pragma unroll
    for (int rr = 0; rr < 2; rr++) {
        int r = wid * 2 + rr;
        float ss = 0.f;
#pragma unroll
        for (int j = 0; j < 16; j++) { float v = s[r * 513 + lid + 32 * j]; ss += v * v; }
#pragma unroll
        for (int o = 16; o > 0; o >>= 1) ss += __shfl_xor_sync(0xffffffffu, ss, o);
        if (lid == 0) sinv[r] = rsqrtf(fmaxf(ss, EPSV));
    }
    __syncthreads();

    // transposed write: nT[d][t0+j]
    float* dstT = (which ? g_nbnT : g_nanT) + (size_t)bb * DD * TT;
#pragma unroll
    for (int i = 0; i < 8; i++) {
        int idx = tid + i * 256;          // float4 units over 512 x 16
        int d = idx >> 2, jq = (idx & 3) * 4;
        float4 o;
        o.x = s[(jq + 0) * 513 + d] * sinv[jq + 0];
        o.y = s[(jq + 1) * 513 + d] * sinv[jq + 1];
        o.z = s[(jq + 2) * 513 + d] * sinv[jq + 2];
        o.w = s[(jq + 3) * 513 + d] * sinv[jq + 3];
        *(float4*)(dstT + (size_t)d * TT + t0 + jq) = o;
    }
    if (which) {
        float* dst = g_nbn + ((size_t)bb * TT + t0) * DD;
#pragma unroll
        for (int i = 0; i < 8; i++) {
            int idx = tid + i * 256;
            int r = idx >> 7, c4 = idx & 127;
            float inv = sinv[r];
            float* sr = s + r * 513 + c4 * 4;
            float4 o = make_float4(sr[0] * inv, sr[1] * inv, sr[2] * inv, sr[3] * inv);
            *(float4*)(dst + (size_t)r * DD + c4 * 4) = o;
        }
    }
}

// ---------------------------------------------------------------------------
// tf32 mma.sync GEMM: D[m,n] = sum_k A[m,k]*B[n,k], both operands K-major.
// CTA tile 128x128, K-chunk 32. 8 warps (2x4), warp tile 64x32,
// mma.sync.m16n8k8. XOR-quad swizzled smem (conflict-free loads+stores).
// Store transposed: C[(n)*512 + m], optional per-m scale.
// ---------------------------------------------------------------------------
__global__ void __launch_bounds__(256, 2) k_gemm_mma(
    const float* __restrict__ Ag, int lda, size_t strideA,
    const float* __restrict__ Bg, int ldb, size_t strideB,
    float* __restrict__ Cg, size_t strideC,
    const float* __restrict__ scale,   // [BB*DD] indexed by m, or null
    int Ktot) {
    __shared__ uint32_t sA[128 * 32];
    __shared__ uint32_t sB[128 * 32];

    int b = blockIdx.z;
    int m0 = blockIdx.x * 128, n0 = blockIdx.y * 128;
    const float* A  = Ag + (size_t)b * strideA + (size_t)m0 * lda;
    const float* Bp = Bg + (size_t)b * strideB + (size_t)n0 * ldb;

    int tid = threadIdx.x, lane = tid & 31, wid = tid >> 5;
    int wm = wid & 1, wn = wid >> 1;   // 2 x 4 warp grid

    float acc[4][4][4];
#pragma unroll
    for (int i = 0; i < 4; i++)
#pragma unroll
        for (int j = 0; j < 4; j++)
#pragma unroll
            for (int k = 0; k < 4; k++) acc[i][j][k] = 0.f;

    int nkt = Ktot / 32;
    for (int kt = 0; kt < nkt; kt++) {
        int k0 = kt * 32;
        // ---- stage global -> smem with tf32 rounding + XOR-quad swizzle ----
#pragma unroll
        for (int i = 0; i < 4; i++) {
            int idx = tid + i * 256;
            int r = idx >> 3, c4 = idx & 7;
            int sw = (c4 ^ (r & 7)) << 2;
            float4 va = *(const float4*)(A + (size_t)r * lda + k0 + c4 * 4);
            uint32_t* da = &sA[r * 32 + sw];
            da[0] = f2tf32(va.x); da[1] = f2tf32(va.y);
            da[2] = f2tf32(va.z); da[3] = f2tf32(va.w);
            float4 vb = *(const float4*)(Bp + (size_t)r * ldb + k0 + c4 * 4);
            uint32_t* db = &sB[r * 32 + sw];
            db[0] = f2tf32(vb.x); db[1] = f2tf32(vb.y);
            db[2] = f2tf32(vb.z); db[3] = f2tf32(vb.w);
        }
        __syncthreads();

        // ---- compute: 4 k-steps of 8 ----
#pragma unroll
        for (int ks = 0; ks < 4; ks++) {
            uint32_t af[4][4], bf[4][2];
#pragma unroll
            for (int mt = 0; mt < 4; mt++) {
                int r = wm * 64 + mt * 16 + (lane >> 2);
                int base = r * 32 + (lane & 3);
                int sw0 = ((ks * 2) ^ (r & 7)) << 2;
                int sw1 = ((ks * 2 + 1) ^ (r & 7)) << 2;
                af[mt][0] = sA[base + sw0];
                af[mt][1] = sA[base + sw0 + 256];  // row+8, same low3 bits
                af[mt][2] = sA[base + sw1];
                af[mt][3] = sA[base + sw1 + 256];
            }
#pragma unroll
            for (int nt = 0; nt < 4; nt++) {
                int r = wn * 32 + nt * 8 + (lane >> 2);
                int base = r * 32 + (lane & 3);
                int sw0 = ((ks * 2) ^ (r & 7)) << 2;
                int sw1 = ((ks * 2 + 1) ^ (r & 7)) << 2;
                bf[nt][0] = sB[base + sw0];
                bf[nt][1] = sB[base + sw1];
            }
#pragma unroll
            for (int mt = 0; mt < 4; mt++)
#pragma unroll
                for (int nt = 0; nt < 4; nt++) {
                    asm volatile(
                        "mma.sync.aligned.m16n8k8.row.col.f32.tf32.tf32.f32 "
                        "{%0,%1,%2,%3}, {%4,%5,%6,%7}, {%8,%9}, {%0,%1,%2,%3};"
                        : "+f"(acc[mt][nt][0]), "+f"(acc[mt][nt][1]),
                          "+f"(acc[mt][nt][2]), "+f"(acc[mt][nt][3])
                        : "r"(af[mt][0]), "r"(af[mt][1]),
                          "r"(af[mt][2]), "r"(af[mt][3]),
                          "r"(bf[nt][0]), "r"(bf[nt][1]));
                }
        }
        __syncthreads();
    }

    // ---- epilogue: transposed store C[(n)*512 + m], optional scale[m] ----
    float* Cb = Cg + (size_t)b * strideC;
    const float* scb = scale ? (scale + (size_t)b * DD) : nullptr;
#pragma unroll
    for (int mt = 0; mt < 4; mt++) {
        int r0 = m0 + wm * 64 + mt * 16 + (lane >> 2);
        float sc0 = scb ? scb[r0] : 1.0f;
        float sc1 = scb ? scb[r0 + 8] : 1.0f;
#pragma unroll
        for (int nt = 0; nt < 4; nt++) {
            int c0 = n0 + wn * 32 + nt * 8 + (lane & 3) * 2;
            Cb[(size_t)c0 * 512 + r0]           = acc[mt][nt][0] * sc0;
            Cb[(size_t)(c0 + 1) * 512 + r0]     = acc[mt][nt][1] * sc0;
            Cb[(size_t)c0 * 512 + r0 + 8]       = acc[mt][nt][2] * sc1;
            Cb[(size_t)(c0 + 1) * 512 + r0 + 8] = acc[mt][nt][3] * sc1;
        }
    }
}

// ---------------------------------------------------------------------------
// Column norms of alpha (= row norms of alphaT). One warp per (b,e).
// ---------------------------------------------------------------------------
__global__ void __launch_bounds__(256) k_colnorm() {
    int gw = (blockIdx.x * blockDim.x + threadIdx.x) >> 5;
    int lane = threadIdx.x & 31;
    if (gw >= BB * DD) return;
    const float4* r4 = (const float4*)(g_alphaT + (size_t)gw * DD);
    float ss = 0.f;
#pragma unroll
    for (int i = 0; i < 4; i++) {
        float4 v = r4[lane + 32 * i];
        ss += v.x * v.x + v.y * v.y + v.z * v.z + v.w * v.w;
    }
#pragma unroll
    for (int o = 16; o > 0; o >>= 1) ss += __shfl_xor_sync(0xffffffffu, ss, o);
    if (lane == 0) g_invcol[gw] = rsqrtf(fmaxf(ss, EPSV));
}

// ---------------------------------------------------------------------------
// Perspective scores: persp = S3 / (sqrt(max(S1,eps))*sqrt(max(S2,eps)))
// ---------------------------------------------------------------------------
__global__ void __launch_bounds__(128) k_persp(const float* __restrict__ inp_a,
                                               const float* __restrict__ W,
                                               float* __restrict__ out, int dup) {
    int row = blockIdx.x;
    int lane = threadIdx.x & 31;
    int w = threadIdx.x >> 5;

    const float4* a4p = (const float4*)(inp_a + (size_t)row * DD);
    const float4* h4p = (const float4*)(g_hmean + (size_t)row * DD);
    float4 a[4], h[4];
#pragma unroll
    for (int i = 0; i < 4; i++) { a[i] = a4p[lane + 32 * i]; h[i] = h4p[lane + 32 * i]; }

#pragma unroll
    for (int pp = 0; pp < 5; pp++) {
        int p = w * 5 + pp;
        const float4* w4p = (const float4*)(W + (size_t)p * DD);
        float s1 = 0.f, s2 = 0.f, s3 = 0.f;
#pragma unroll
        for (int i = 0; i < 4; i++) {
            float4 wv = w4p[lane + 32 * i];
            float w2;
            w2 = wv.x * wv.x; s1 += a[i].x * a[i].x * w2; s2 += h[i].x * h[i].x * w2; s3 += a[i].x * h[i].x * w2;
            w2 = wv.y * wv.y; s1 += a[i].y * a[i].y * w2; s2 += h[i].y * h[i].y * w2; s3 += a[i].y * h[i].y * w2;
            w2 = wv.z * wv.z; s1 += a[i].z * a[i].z * w2; s2 += h[i].z * h[i].z * w2; s3 += a[i].z * h[i].z * w2;
            w2 = wv.w * wv.w; s1 += a[i].w * a[i].w * w2; s2 += h[i].w * h[i].w * w2; s3 += a[i].w * h[i].w * w2;
        }
#pragma unroll
        for (int o = 16; o > 0; o >>= 1) {
            s1 += __shfl_xor_sync(0xffffffffu, s1, o);
            s2 += __shfl_xor_sync(0xffffffffu, s2, o);
            s3 += __shfl_xor_sync(0xffffffffu, s3, o);
        }
        if (lane == 0) {
            float v = s3 * rsqrtf(fmaxf(s1, EPSV)) * rsqrtf(fmaxf(s2, EPSV));
            out[(size_t)row * PP + p] = v;
            if (dup) out[(size_t)BB * TT * PP + (size_t)row * PP + p] = v;
        }
    }
}

// ---------------------------------------------------------------------------
extern "C" void kernel_launch(void* const* d_in, const int* in_sizes, int n_in,
                              void* d_out, int out_size) {
    const float* inp_a = (const float*)d_in[0];
    const float* inp_b = (const float*)d_in[1];
    const float* W     = (const float*)d_in[2];
    float* out = (float*)d_out;
    int dup = (out_size >= 2 * BB * TT * PP) ? 1 : 0;

    void *p_nbn, *p_nbnT, *p_nanT, *p_alphaT, *p_invcol, *p_hmean;
    cudaGetSymbolAddress(&p_nbn, g_nbn);
    cudaGetSymbolAddress(&p_nbnT, g_nbnT);
    cudaGetSymbolAddress(&p_nanT, g_nanT);
    cudaGetSymbolAddress(&p_alphaT, g_alphaT);
    cudaGetSymbolAddress(&p_invcol, g_invcol);
    cudaGetSymbolAddress(&p_hmean, g_hmean);

    // 1) normalize + transpose
    k_normT<<<dim3(TT / 16, BB, 2), 256>>>(inp_a, inp_b);

    // 2) GEMM1: alphaT[e][d] = sum_t nbnT[d,t]*nanT[e,t]  (M=512 d, N=512 e, K=256 t)
    k_gemm_mma<<<dim3(4, 4, BB), 256>>>(
        (const float*)p_nbnT, TT, (size_t)DD * TT,
        (const float*)p_nanT, TT, (size_t)DD * TT,
        (float*)p_alphaT, (size_t)DD * DD, nullptr, TT);

    // 3) inverse column norms of alpha (rows of alphaT)
    k_colnorm<<<(BB * DD) / 8, 256>>>();

    // 4) GEMM2: hmean[t][e] = (sum_d alphaT[e,d]*nbn[t,d]) * invcol[e]
    //    (M=512 e, N=256 t, K=512 d)
    k_gemm_mma<<<dim3(4, 2, BB), 256>>>(
        (const float*)p_alphaT, DD, (size_t)DD * DD,
        (const float*)p_nbn, DD, (size_t)TT * DD,
        (float*)p_hmean, (size_t)TT * DD, (const float*)p_invcol, DD);

    // 5) perspective scores
    k_persp<<<BB * TT, 128>>>(inp_a, W, out, dup);
}